// round 2
// baseline (speedup 1.0000x reference)
#include <cuda_runtime.h>
#include <math.h>

#define N_NODES 50000
#define N_EDGES 800000
#define F 64
#define E_TOT (N_EDGES + N_NODES)
#define NEG_ATT 0.2f
#define NEG_ACT 0.01f

// -------- scratch (device globals; no allocation allowed) --------
__device__ float g_h  [N_NODES * F];  // h = x @ W
__device__ float g_out[N_NODES * F];  // aggregated output accumulator
__device__ float g_x1 [N_NODES * F];  // layer-1 activated output (input to layer 2)
__device__ float g_as [N_NODES];
__device__ float g_ad [N_NODES];
__device__ float g_m  [N_NODES];
__device__ float g_z  [N_NODES];
__device__ float g_e  [E_TOT];

// -------- float atomic max via int/uint ordering trick --------
__device__ __forceinline__ void atomicMaxF(float* addr, float value) {
    if (value >= 0.0f)
        atomicMax((int*)addr, __float_as_int(value));
    else
        atomicMin((unsigned int*)addr, __float_as_uint(value));
}

// -------- init: zero accumulator, -inf max, 0 sum --------
__global__ void init_kernel() {
    int i0 = blockIdx.x * blockDim.x + threadIdx.x;
    int stride = gridDim.x * blockDim.x;
    for (int i = i0; i < N_NODES * F; i += stride) g_out[i] = 0.0f;
    for (int i = i0; i < N_NODES; i += stride) { g_m[i] = -INFINITY; g_z[i] = 0.0f; }
}

// -------- fused GEMM + attention dot products --------
// blockDim = (64, 4). Each (ty) row computes h[row,:] and alpha_s/alpha_d[row].
// use_x1 != 0 -> read from g_x1 instead of x.
__global__ void gemm_alpha_kernel(const float* __restrict__ x,
                                  const float* __restrict__ W,
                                  const float* __restrict__ a_s,
                                  const float* __restrict__ a_d,
                                  int use_x1) {
    __shared__ float Ws[F][F];        // 16 KB, row-major: Ws[k][col]
    __shared__ float xs[4][F];
    __shared__ float red_s[4][2];
    __shared__ float red_d[4][2];

    const int tx = threadIdx.x;       // col 0..63
    const int ty = threadIdx.y;       // 0..3
    const int tid = ty * 64 + tx;

    for (int i = tid; i < F * F; i += 256) Ws[i >> 6][i & 63] = W[i];

    const int row = blockIdx.x * 4 + ty;
    if (row < N_NODES) {
        const float* xin = use_x1 ? g_x1 : x;
        xs[ty][tx] = xin[row * F + tx];
    }
    __syncthreads();

    if (row < N_NODES) {
        float acc = 0.0f;
#pragma unroll
        for (int k = 0; k < F; k++) acc = fmaf(xs[ty][k], Ws[k][tx], acc);
        g_h[row * F + tx] = acc;

        float ps = acc * a_s[tx];
        float pd = acc * a_d[tx];
#pragma unroll
        for (int o = 16; o > 0; o >>= 1) {
            ps += __shfl_down_sync(0xffffffffu, ps, o);
            pd += __shfl_down_sync(0xffffffffu, pd, o);
        }
        const int lane = tx & 31, w = tx >> 5;
        if (lane == 0) { red_s[ty][w] = ps; red_d[ty][w] = pd; }
    }
    __syncthreads();
    if (row < N_NODES && tx == 0) {
        g_as[row] = red_s[ty][0] + red_s[ty][1];
        g_ad[row] = red_d[ty][0] + red_d[ty][1];
    }
}

// -------- edge pass 1: e = leaky(as[src] + ad[dst]); segment max --------
__global__ void edge_max_kernel(const int* __restrict__ ei) {
    int e = blockIdx.x * blockDim.x + threadIdx.x;
    if (e >= E_TOT) return;
    int src, dst;
    if (e < N_EDGES) { src = ei[e]; dst = ei[N_EDGES + e]; }
    else             { src = dst = e - N_EDGES; }
    float v = g_as[src] + g_ad[dst];
    v = v > 0.0f ? v : NEG_ATT * v;
    g_e[e] = v;
    atomicMaxF(&g_m[dst], v);
}

// -------- edge pass 2: ex = exp(e - m[dst]); segment sum --------
__global__ void edge_exp_kernel(const int* __restrict__ ei) {
    int e = blockIdx.x * blockDim.x + threadIdx.x;
    if (e >= E_TOT) return;
    int dst = (e < N_EDGES) ? ei[N_EDGES + e] : (e - N_EDGES);
    float ex = expf(g_e[e] - g_m[dst]);
    g_e[e] = ex;
    atomicAdd(&g_z[dst], ex);
}

// -------- edge pass 3: out[dst] += h[src] * alpha (warp per edge) --------
__global__ void edge_agg_kernel(const int* __restrict__ ei) {
    int gt = blockIdx.x * blockDim.x + threadIdx.x;
    int warp = gt >> 5;
    int lane = gt & 31;
    if (warp >= E_TOT) return;
    int src, dst;
    if (warp < N_EDGES) { src = ei[warp]; dst = ei[N_EDGES + warp]; }
    else                { src = dst = warp - N_EDGES; }
    float alpha = g_e[warp] / (g_z[dst] + 1e-16f);
    float2 hv = ((const float2*)(g_h + (size_t)src * F))[lane];
    float* outp = g_out + (size_t)dst * F + 2 * lane;
    atomicAdd(outp,     hv.x * alpha);
    atomicAdd(outp + 1, hv.y * alpha);
}

// -------- finalize layer 1: bias + leaky -> g_x1 --------
__global__ void finalize1_kernel(const float* __restrict__ b) {
    int i = blockIdx.x * blockDim.x + threadIdx.x;
    if (i >= N_NODES * F) return;
    float v = g_out[i] + b[i & 63];
    g_x1[i] = v > 0.0f ? v : NEG_ACT * v;
}

// -------- finalize layer 2: bias + leaky + residual -> d_out --------
__global__ void finalize2_kernel(const float* __restrict__ b,
                                 const float* __restrict__ x,
                                 float* __restrict__ out) {
    int i = blockIdx.x * blockDim.x + threadIdx.x;
    if (i >= N_NODES * F) return;
    float v = g_out[i] + b[i & 63];
    v = v > 0.0f ? v : NEG_ACT * v;
    out[i] = v + x[i];
}

extern "C" void kernel_launch(void* const* d_in, const int* in_sizes, int n_in,
                              void* d_out, int out_size) {
    const float* x    = (const float*)d_in[0];
    const int*   ei   = (const int*)d_in[1];     // int64 in reference -> int32 on device
    const float* W0   = (const float*)d_in[2];
    const float* as0  = (const float*)d_in[3];
    const float* ad0  = (const float*)d_in[4];
    const float* b0   = (const float*)d_in[5];
    const float* W1   = (const float*)d_in[6];
    const float* as1  = (const float*)d_in[7];
    const float* ad1  = (const float*)d_in[8];
    const float* b1   = (const float*)d_in[9];
    float*       out  = (float*)d_out;

    const int TB = 256;
    const int initGrid = (N_NODES * F + TB - 1) / TB;
    const int gemmGrid = (N_NODES + 3) / 4;
    const int edgeGrid = (E_TOT + TB - 1) / TB;
    const int aggGrid  = (E_TOT * 32 + TB - 1) / TB;   // warp per edge
    const int finGrid  = (N_NODES * F + TB - 1) / TB;

    dim3 gemmBlock(64, 4);

    // ---- layer 0 ----
    init_kernel<<<initGrid, TB>>>();
    gemm_alpha_kernel<<<gemmGrid, gemmBlock>>>(x, W0, as0, ad0, 0);
    edge_max_kernel<<<edgeGrid, TB>>>(ei);
    edge_exp_kernel<<<edgeGrid, TB>>>(ei);
    edge_agg_kernel<<<aggGrid, TB>>>(ei);
    finalize1_kernel<<<finGrid, TB>>>(b0);

    // ---- layer 1 ----
    init_kernel<<<initGrid, TB>>>();
    gemm_alpha_kernel<<<gemmGrid, gemmBlock>>>(x, W1, as1, ad1, 1);
    edge_max_kernel<<<edgeGrid, TB>>>(ei);
    edge_exp_kernel<<<edgeGrid, TB>>>(ei);
    edge_agg_kernel<<<aggGrid, TB>>>(ei);
    finalize2_kernel<<<finGrid, TB>>>(b1, x, out);
}

// round 3
// speedup vs baseline: 1.5319x; 1.5319x over previous
#include <cuda_runtime.h>
#include <math.h>

#define N_NODES 50000
#define N_EDGES 800000
#define F 64
#define E_TOT (N_EDGES + N_NODES)
#define NEG_ATT 0.2f
#define NEG_ACT 0.01f
#define GEMM_ROWS 32

// -------- scratch (device globals; 16B-aligned for vector ops) --------
__device__ __align__(16) float g_h  [N_NODES * F];
__device__ __align__(16) float g_out[N_NODES * F];
__device__ __align__(16) float g_x1 [N_NODES * F];
__device__ float g_as [N_NODES];
__device__ float g_ad [N_NODES];
__device__ float g_m  [N_NODES];
__device__ float g_z  [N_NODES];
__device__ float g_e  [E_TOT];

// -------- float atomic max via int/uint ordering trick --------
__device__ __forceinline__ void atomicMaxF(float* addr, float value) {
    if (value >= 0.0f)
        atomicMax((int*)addr, __float_as_int(value));
    else
        atomicMin((unsigned int*)addr, __float_as_uint(value));
}

// -------- vectorized global reduction (sm_90+) --------
__device__ __forceinline__ void redAddV4(float* addr, float x, float y, float z, float w) {
    asm volatile("red.global.add.v4.f32 [%0], {%1, %2, %3, %4};"
                 :: "l"(addr), "f"(x), "f"(y), "f"(z), "f"(w) : "memory");
}

// -------- full init (layer 0): zero accum, -inf max, 0 sum --------
__global__ void init_kernel() {
    int i0 = blockIdx.x * blockDim.x + threadIdx.x;
    int stride = gridDim.x * blockDim.x;
    for (int i = i0; i < N_NODES * F; i += stride) g_out[i] = 0.0f;
    for (int i = i0; i < N_NODES; i += stride) { g_m[i] = -INFINITY; g_z[i] = 0.0f; }
}

// -------- small init (between layers): reset m/z only --------
__global__ void init_mz_kernel() {
    int i = blockIdx.x * blockDim.x + threadIdx.x;
    if (i < N_NODES) { g_m[i] = -INFINITY; g_z[i] = 0.0f; }
}

// -------- GEMM: h = x @ W, 32 rows per block (W loaded once per 32 rows) ----
__global__ void gemm_kernel(const float* __restrict__ x,
                            const float* __restrict__ W,
                            int use_x1) {
    __shared__ float Ws[F][F];            // 16 KB
    __shared__ float xs[GEMM_ROWS][F];    // 8 KB

    const int tx = threadIdx.x;           // 0..63
    const int ty = threadIdx.y;           // 0..3
    const int tid = ty * 64 + tx;
    const int row0 = blockIdx.x * GEMM_ROWS;

    for (int i = tid; i < F * F; i += 256) Ws[i >> 6][i & 63] = W[i];

    const float* xin = use_x1 ? g_x1 : x;
    for (int i = tid; i < GEMM_ROWS * F; i += 256) {
        int r = i >> 6, c = i & 63;
        int row = row0 + r;
        xs[r][c] = (row < N_NODES) ? xin[row * F + c] : 0.0f;
    }
    __syncthreads();

#pragma unroll
    for (int r = ty; r < GEMM_ROWS; r += 4) {
        int row = row0 + r;
        if (row >= N_NODES) break;
        float acc = 0.0f;
#pragma unroll
        for (int k = 0; k < F; k++) acc = fmaf(xs[r][k], Ws[k][tx], acc);
        g_h[row * F + tx] = acc;
    }
}

// -------- alpha: as = h @ a_src, ad = h @ a_dst (one warp per node) --------
__global__ void alpha_kernel(const float* __restrict__ a_s,
                             const float* __restrict__ a_d) {
    int gt = blockIdx.x * blockDim.x + threadIdx.x;
    int node = gt >> 5;
    int lane = gt & 31;
    if (node >= N_NODES) return;
    float2 hv  = ((const float2*)(g_h + (size_t)node * F))[lane];
    float2 av  = ((const float2*)a_s)[lane];
    float2 bv  = ((const float2*)a_d)[lane];
    float ps = hv.x * av.x + hv.y * av.y;
    float pd = hv.x * bv.x + hv.y * bv.y;
#pragma unroll
    for (int o = 16; o > 0; o >>= 1) {
        ps += __shfl_down_sync(0xffffffffu, ps, o);
        pd += __shfl_down_sync(0xffffffffu, pd, o);
    }
    if (lane == 0) { g_as[node] = ps; g_ad[node] = pd; }
}

// -------- edge pass 1: e = leaky(as[src] + ad[dst]); segment max --------
__global__ void edge_max_kernel(const int* __restrict__ ei) {
    int e = blockIdx.x * blockDim.x + threadIdx.x;
    if (e >= E_TOT) return;
    int src, dst;
    if (e < N_EDGES) { src = ei[e]; dst = ei[N_EDGES + e]; }
    else             { src = dst = e - N_EDGES; }
    float v = g_as[src] + g_ad[dst];
    v = v > 0.0f ? v : NEG_ATT * v;
    g_e[e] = v;
    atomicMaxF(&g_m[dst], v);
}

// -------- edge pass 2 (fused): ex = exp(e - m[dst]); z += ex;
//          out[dst] += h[src] * ex   (16 threads/edge, v4 reductions) --------
__global__ void edge_fused_kernel(const int* __restrict__ ei) {
    int gt = blockIdx.x * blockDim.x + threadIdx.x;
    int e   = gt >> 4;
    int sub = gt & 15;
    if (e >= E_TOT) return;
    int src, dst;
    if (e < N_EDGES) { src = ei[e]; dst = ei[N_EDGES + e]; }
    else             { src = dst = e - N_EDGES; }
    float ex = __expf(g_e[e] - g_m[dst]);
    if (sub == 0) atomicAdd(&g_z[dst], ex);
    float4 hv = ((const float4*)(g_h + (size_t)src * F))[sub];
    redAddV4(g_out + (size_t)dst * F + 4 * sub,
             hv.x * ex, hv.y * ex, hv.z * ex, hv.w * ex);
}

// -------- finalize layer 1: normalize + bias + leaky -> g_x1; zero accum ----
__global__ void finalize1_kernel(const float* __restrict__ b) {
    int i = blockIdx.x * blockDim.x + threadIdx.x;
    if (i >= N_NODES * F) return;
    float v = g_out[i] / (g_z[i >> 6] + 1e-16f) + b[i & 63];
    g_x1[i] = v > 0.0f ? v : NEG_ACT * v;
    g_out[i] = 0.0f;   // re-init accumulator for layer 2
}

// -------- finalize layer 2: normalize + bias + leaky + residual -> out ------
__global__ void finalize2_kernel(const float* __restrict__ b,
                                 const float* __restrict__ x,
                                 float* __restrict__ out) {
    int i = blockIdx.x * blockDim.x + threadIdx.x;
    if (i >= N_NODES * F) return;
    float v = g_out[i] / (g_z[i >> 6] + 1e-16f) + b[i & 63];
    v = v > 0.0f ? v : NEG_ACT * v;
    out[i] = v + x[i];
}

extern "C" void kernel_launch(void* const* d_in, const int* in_sizes, int n_in,
                              void* d_out, int out_size) {
    const float* x    = (const float*)d_in[0];
    const int*   ei   = (const int*)d_in[1];   // int64 ref -> int32 on device
    const float* W0   = (const float*)d_in[2];
    const float* as0  = (const float*)d_in[3];
    const float* ad0  = (const float*)d_in[4];
    const float* b0   = (const float*)d_in[5];
    const float* W1   = (const float*)d_in[6];
    const float* as1  = (const float*)d_in[7];
    const float* ad1  = (const float*)d_in[8];
    const float* b1   = (const float*)d_in[9];
    float*       out  = (float*)d_out;

    const int TB = 256;
    const int initGrid  = (N_NODES * F + TB - 1) / TB;
    const int mzGrid    = (N_NODES + TB - 1) / TB;
    const int gemmGrid  = (N_NODES + GEMM_ROWS - 1) / GEMM_ROWS;
    const int alphaGrid = (N_NODES * 32 + TB - 1) / TB;
    const int edgeGrid  = (E_TOT + TB - 1) / TB;
    const int fusedGrid = ((long long)E_TOT * 16 + TB - 1) / TB;
    const int finGrid   = (N_NODES * F + TB - 1) / TB;

    dim3 gemmBlock(64, 4);

    // ---- layer 0 ----
    init_kernel<<<initGrid, TB>>>();
    gemm_kernel<<<gemmGrid, gemmBlock>>>(x, W0, 0);
    alpha_kernel<<<alphaGrid, TB>>>(as0, ad0);
    edge_max_kernel<<<edgeGrid, TB>>>(ei);
    edge_fused_kernel<<<fusedGrid, TB>>>(ei);
    finalize1_kernel<<<finGrid, TB>>>(b0);

    // ---- layer 1 ----
    init_mz_kernel<<<mzGrid, TB>>>();
    gemm_kernel<<<gemmGrid, gemmBlock>>>(x, W1, 1);
    alpha_kernel<<<alphaGrid, TB>>>(as1, ad1);
    edge_max_kernel<<<edgeGrid, TB>>>(ei);
    edge_fused_kernel<<<fusedGrid, TB>>>(ei);
    finalize2_kernel<<<finGrid, TB>>>(b1, x, out);
}

// round 4
// speedup vs baseline: 1.6677x; 1.0886x over previous
#include <cuda_runtime.h>
#include <math.h>

#define N_NODES 50000
#define N_EDGES 800000
#define F 64
#define E_TOT (N_EDGES + N_NODES)
#define NEG_ATT 0.2f
#define NEG_ACT 0.01f
#define GEMM_ROWS 32

// -------- scratch (device globals; 16B-aligned for vector ops) --------
__device__ __align__(16) float g_h  [N_NODES * F];
__device__ __align__(16) float g_out[N_NODES * F];
__device__ __align__(16) float g_x1 [N_NODES * F];
__device__ float g_as [N_NODES];
__device__ float g_ad [N_NODES];
__device__ float g_z  [N_NODES];

// -------- vectorized global reduction (sm_90+) --------
__device__ __forceinline__ void redAddV4(float* addr, float x, float y, float z, float w) {
    asm volatile("red.global.add.v4.f32 [%0], {%1, %2, %3, %4};"
                 :: "l"(addr), "f"(x), "f"(y), "f"(z), "f"(w) : "memory");
}

// -------- full init (layer 0): zero accum + z --------
__global__ void init_kernel() {
    int i0 = blockIdx.x * blockDim.x + threadIdx.x;
    int stride = gridDim.x * blockDim.x;
    for (int i = i0; i < N_NODES * F; i += stride) g_out[i] = 0.0f;
    for (int i = i0; i < N_NODES; i += stride) g_z[i] = 0.0f;
}

// -------- small init (between layers): zero z only --------
__global__ void init_z_kernel() {
    int i = blockIdx.x * blockDim.x + threadIdx.x;
    if (i < N_NODES) g_z[i] = 0.0f;
}

// -------- GEMM: h = x @ W, 32 rows per block --------
__global__ void gemm_kernel(const float* __restrict__ x,
                            const float* __restrict__ W,
                            int use_x1) {
    __shared__ float Ws[F][F];            // 16 KB
    __shared__ float xs[GEMM_ROWS][F];    // 8 KB

    const int tx = threadIdx.x;           // 0..63
    const int ty = threadIdx.y;           // 0..3
    const int tid = ty * 64 + tx;
    const int row0 = blockIdx.x * GEMM_ROWS;

    for (int i = tid; i < F * F; i += 256) Ws[i >> 6][i & 63] = W[i];

    const float* xin = use_x1 ? g_x1 : x;
    for (int i = tid; i < GEMM_ROWS * F; i += 256) {
        int r = i >> 6, c = i & 63;
        int row = row0 + r;
        xs[r][c] = (row < N_NODES) ? xin[row * F + c] : 0.0f;
    }
    __syncthreads();

#pragma unroll
    for (int r = ty; r < GEMM_ROWS; r += 4) {
        int row = row0 + r;
        if (row >= N_NODES) break;
        float acc = 0.0f;
#pragma unroll
        for (int k = 0; k < F; k++) acc = fmaf(xs[r][k], Ws[k][tx], acc);
        g_h[row * F + tx] = acc;
    }
}

// -------- alpha: as = h @ a_src, ad = h @ a_dst (one warp per node) --------
__global__ void alpha_kernel(const float* __restrict__ a_s,
                             const float* __restrict__ a_d) {
    int gt = blockIdx.x * blockDim.x + threadIdx.x;
    int node = gt >> 5;
    int lane = gt & 31;
    if (node >= N_NODES) return;
    float2 hv  = ((const float2*)(g_h + (size_t)node * F))[lane];
    float2 av  = ((const float2*)a_s)[lane];
    float2 bv  = ((const float2*)a_d)[lane];
    float ps = hv.x * av.x + hv.y * av.y;
    float pd = hv.x * bv.x + hv.y * bv.y;
#pragma unroll
    for (int o = 16; o > 0; o >>= 1) {
        ps += __shfl_down_sync(0xffffffffu, ps, o);
        pd += __shfl_down_sync(0xffffffffu, pd, o);
    }
    if (lane == 0) { g_as[node] = ps; g_ad[node] = pd; }
}

// -------- fused edge pass (no max shift; shifts cancel in alpha = ex/z):
//   ex = exp(leaky(as[src]+ad[dst])); z[dst] += ex; out[dst] += h[src]*ex
//   16 threads/edge; leader computes scalars + broadcasts via shfl.
//   E_TOT*16 is a multiple of 256, so every thread maps to a valid edge. --
__global__ void edge_fused_kernel(const int* __restrict__ ei) {
    int gt = blockIdx.x * blockDim.x + threadIdx.x;
    int e   = gt >> 4;
    int sub = gt & 15;
    int src = 0, dst = 0;
    float ex = 0.0f;
    if (sub == 0) {
        if (e < N_EDGES) { src = ei[e]; dst = ei[N_EDGES + e]; }
        else             { src = dst = e - N_EDGES; }
        float v = g_as[src] + g_ad[dst];
        v = v > 0.0f ? v : NEG_ATT * v;
        ex = __expf(v);
        atomicAdd(&g_z[dst], ex);
    }
    src = __shfl_sync(0xffffffffu, src, 0, 16);
    dst = __shfl_sync(0xffffffffu, dst, 0, 16);
    ex  = __shfl_sync(0xffffffffu, ex,  0, 16);
    float4 hv = ((const float4*)(g_h + (size_t)src * F))[sub];
    redAddV4(g_out + (size_t)dst * F + 4 * sub,
             hv.x * ex, hv.y * ex, hv.z * ex, hv.w * ex);
}

// -------- finalize layer 1: normalize + bias + leaky -> g_x1; zero accum ----
__global__ void finalize1_kernel(const float* __restrict__ b) {
    int i = blockIdx.x * blockDim.x + threadIdx.x;
    if (i >= N_NODES * F) return;
    float v = g_out[i] / (g_z[i >> 6] + 1e-16f) + b[i & 63];
    g_x1[i] = v > 0.0f ? v : NEG_ACT * v;
    g_out[i] = 0.0f;   // re-init accumulator for layer 2
}

// -------- finalize layer 2: normalize + bias + leaky + residual -> out ------
__global__ void finalize2_kernel(const float* __restrict__ b,
                                 const float* __restrict__ x,
                                 float* __restrict__ out) {
    int i = blockIdx.x * blockDim.x + threadIdx.x;
    if (i >= N_NODES * F) return;
    float v = g_out[i] / (g_z[i >> 6] + 1e-16f) + b[i & 63];
    v = v > 0.0f ? v : NEG_ACT * v;
    out[i] = v + x[i];
}

extern "C" void kernel_launch(void* const* d_in, const int* in_sizes, int n_in,
                              void* d_out, int out_size) {
    const float* x    = (const float*)d_in[0];
    const int*   ei   = (const int*)d_in[1];   // int64 ref -> int32 on device
    const float* W0   = (const float*)d_in[2];
    const float* as0  = (const float*)d_in[3];
    const float* ad0  = (const float*)d_in[4];
    const float* b0   = (const float*)d_in[5];
    const float* W1   = (const float*)d_in[6];
    const float* as1  = (const float*)d_in[7];
    const float* ad1  = (const float*)d_in[8];
    const float* b1   = (const float*)d_in[9];
    float*       out  = (float*)d_out;

    const int TB = 256;
    const int initGrid  = (N_NODES * F + TB - 1) / TB;
    const int zGrid     = (N_NODES + TB - 1) / TB;
    const int gemmGrid  = (N_NODES + GEMM_ROWS - 1) / GEMM_ROWS;
    const int alphaGrid = (N_NODES * 32 + TB - 1) / TB;
    const int fusedGrid = (int)(((long long)E_TOT * 16) / TB);  // exact
    const int finGrid   = (N_NODES * F + TB - 1) / TB;

    dim3 gemmBlock(64, 4);

    // ---- layer 0 ----
    init_kernel<<<initGrid, TB>>>();
    gemm_kernel<<<gemmGrid, gemmBlock>>>(x, W0, 0);
    alpha_kernel<<<alphaGrid, TB>>>(as0, ad0);
    edge_fused_kernel<<<fusedGrid, TB>>>(ei);
    finalize1_kernel<<<finGrid, TB>>>(b0);

    // ---- layer 1 ----
    init_z_kernel<<<zGrid, TB>>>();
    gemm_kernel<<<gemmGrid, gemmBlock>>>(x, W1, 1);
    alpha_kernel<<<alphaGrid, TB>>>(as1, ad1);
    edge_fused_kernel<<<fusedGrid, TB>>>(ei);
    finalize2_kernel<<<finGrid, TB>>>(b1, x, out);
}

// round 6
// speedup vs baseline: 1.9436x; 1.1654x over previous
#include <cuda_runtime.h>
#include <math.h>

#define N_NODES 50000
#define N_EDGES 800000
#define F 64
#define E_TOT (N_EDGES + N_NODES)
#define NEG_ATT 0.2f
#define NEG_ACT 0.01f
#define GEMM_ROWS 32

// -------- scratch (device globals; referenced ONLY inside kernels) --------
__device__ __align__(16) float g_h  [N_NODES * F];
__device__ __align__(16) float g_x1 [N_NODES * F];
__device__ float g_as [N_NODES];
__device__ float g_ad [N_NODES];
__device__ int   g_cnt[N_NODES];
__device__ int   g_cur[N_NODES];
__device__ int   g_rowstart[N_NODES + 1];
__device__ int   g_csrc[E_TOT];

// ================= CSR build (once per launch; reused by both layers) ======

__global__ void zero_cnt_kernel() {
    int i = blockIdx.x * blockDim.x + threadIdx.x;
    if (i < N_NODES) g_cnt[i] = 0;
}

__global__ void hist_kernel(const int* __restrict__ ei) {
    int e = blockIdx.x * blockDim.x + threadIdx.x;
    if (e >= E_TOT) return;
    int dst = (e < N_EDGES) ? ei[N_EDGES + e] : (e - N_EDGES);
    atomicAdd(&g_cnt[dst], 1);
}

// single-block chunked scan: row_start = exclusive prefix of cnt
__global__ void scan_kernel() {
    const int tid = threadIdx.x;
    const int lane = tid & 31, wid = tid >> 5;
    __shared__ int wsum[32];
    __shared__ int s_carry;
    if (tid == 0) s_carry = 0;
    __syncthreads();
    for (int base = 0; base < N_NODES; base += 1024) {
        int i = base + tid;
        int v = (i < N_NODES) ? g_cnt[i] : 0;
        int incl = v;
#pragma unroll
        for (int o = 1; o < 32; o <<= 1) {
            int t = __shfl_up_sync(0xffffffffu, incl, o);
            if (lane >= o) incl += t;
        }
        if (lane == 31) wsum[wid] = incl;
        __syncthreads();
        if (wid == 0) {
            int w = wsum[lane];
#pragma unroll
            for (int o = 1; o < 32; o <<= 1) {
                int t = __shfl_up_sync(0xffffffffu, w, o);
                if (lane >= o) w += t;
            }
            wsum[lane] = w;
        }
        __syncthreads();
        int offset = (wid > 0 ? wsum[wid - 1] : 0) + s_carry;
        int total = wsum[31];
        if (i < N_NODES) g_rowstart[i + 1] = offset + incl;
        __syncthreads();
        if (tid == 0) s_carry += total;
        __syncthreads();
    }
    if (tid == 0) g_rowstart[0] = 0;
}

__global__ void cursor_kernel() {
    int i = blockIdx.x * blockDim.x + threadIdx.x;
    if (i < N_NODES) g_cur[i] = g_rowstart[i];
}

__global__ void scatter_kernel(const int* __restrict__ ei) {
    int e = blockIdx.x * blockDim.x + threadIdx.x;
    if (e >= E_TOT) return;
    int src, dst;
    if (e < N_EDGES) { src = ei[e]; dst = ei[N_EDGES + e]; }
    else             { src = dst = e - N_EDGES; }
    int pos = atomicAdd(&g_cur[dst], 1);
    g_csrc[pos] = src;
}

// ========== fused GEMM + attention dots: h = x@W, as = h@a_s, ad = h@a_d ====
__global__ void gemm_alpha_kernel(const float* __restrict__ x,
                                  const float* __restrict__ W,
                                  const float* __restrict__ a_s,
                                  const float* __restrict__ a_d,
                                  int use_x1) {
    __shared__ float Ws[F][F];            // 16 KB
    __shared__ float xs[GEMM_ROWS][F];    // 8 KB
    __shared__ float red_s[GEMM_ROWS][2];
    __shared__ float red_d[GEMM_ROWS][2];

    const int tx = threadIdx.x;           // 0..63
    const int ty = threadIdx.y;           // 0..3
    const int tid = ty * 64 + tx;
    const int row0 = blockIdx.x * GEMM_ROWS;

    for (int i = tid; i < F * F; i += 256) Ws[i >> 6][i & 63] = W[i];

    const float* xin = use_x1 ? g_x1 : x;
    for (int i = tid; i < GEMM_ROWS * F; i += 256) {
        int r = i >> 6, c = i & 63;
        int row = row0 + r;
        xs[r][c] = (row < N_NODES) ? xin[row * F + c] : 0.0f;
    }
    __syncthreads();

    const float asc = a_s[tx];
    const float adc = a_d[tx];

#pragma unroll
    for (int r = ty; r < GEMM_ROWS; r += 4) {
        int row = row0 + r;
        float acc = 0.0f;
#pragma unroll
        for (int k = 0; k < F; k++) acc = fmaf(xs[r][k], Ws[k][tx], acc);
        if (row < N_NODES) g_h[row * F + tx] = acc;

        float ps = acc * asc;
        float pd = acc * adc;
#pragma unroll
        for (int o = 16; o > 0; o >>= 1) {
            ps += __shfl_down_sync(0xffffffffu, ps, o);
            pd += __shfl_down_sync(0xffffffffu, pd, o);
        }
        if ((tx & 31) == 0) { red_s[r][tx >> 5] = ps; red_d[r][tx >> 5] = pd; }
    }
    __syncthreads();
    if (tid < GEMM_ROWS) {
        int row = row0 + tid;
        if (row < N_NODES) {
            g_as[row] = red_s[tid][0] + red_s[tid][1];
            g_ad[row] = red_d[tid][0] + red_d[tid][1];
        }
    }
}

// ========== gather aggregation: warp per dst node, atomic-free =============
// acc = sum_j h[src_j] * exp(leaky(as[src_j]+ad[n]));  z = sum_j exp(...)
// layer 0: g_x1[n] = leaky(acc/z + b)
// layer 1: out[n]  = leaky(acc/z + b) + x[n]
__global__ void gather_kernel(const float* __restrict__ b,
                              const float* __restrict__ xres,
                              float* __restrict__ outp,
                              int final_layer) {
    int gt = blockIdx.x * blockDim.x + threadIdx.x;
    int node = gt >> 5;
    int lane = gt & 31;
    if (node >= N_NODES) return;

    int beg = g_rowstart[node];
    int end = g_rowstart[node + 1];
    float ad_n = g_ad[node];

    float2 acc = make_float2(0.0f, 0.0f);
    float zsum = 0.0f;

    for (int c = beg; c < end; c += 32) {
        int j = c + lane;
        int s = 0;
        float ex = 0.0f;
        if (j < end) {
            s = g_csrc[j];
            float v = g_as[s] + ad_n;
            v = v > 0.0f ? v : NEG_ATT * v;
            ex = __expf(v);
            zsum += ex;
        }
        int cnt = min(32, end - c);
        for (int k = 0; k < cnt; k++) {
            int   sk  = __shfl_sync(0xffffffffu, s, k);
            float exk = __shfl_sync(0xffffffffu, ex, k);
            float2 hv = ((const float2*)(g_h + (size_t)sk * F))[lane];
            acc.x = fmaf(hv.x, exk, acc.x);
            acc.y = fmaf(hv.y, exk, acc.y);
        }
    }
#pragma unroll
    for (int o = 16; o > 0; o >>= 1) zsum += __shfl_xor_sync(0xffffffffu, zsum, o);
    float inv = 1.0f / (zsum + 1e-16f);

    float2 bv = ((const float2*)b)[lane];
    float vx = fmaf(acc.x, inv, bv.x);
    float vy = fmaf(acc.y, inv, bv.y);
    vx = vx > 0.0f ? vx : NEG_ACT * vx;
    vy = vy > 0.0f ? vy : NEG_ACT * vy;

    if (final_layer) {
        float2 xr = ((const float2*)(xres + (size_t)node * F))[lane];
        vx += xr.x;
        vy += xr.y;
        ((float2*)(outp + (size_t)node * F))[lane] = make_float2(vx, vy);
    } else {
        // write to device-global g_x1 directly (NOT passed from host!)
        ((float2*)(g_x1 + (size_t)node * F))[lane] = make_float2(vx, vy);
    }
}

extern "C" void kernel_launch(void* const* d_in, const int* in_sizes, int n_in,
                              void* d_out, int out_size) {
    const float* x    = (const float*)d_in[0];
    const int*   ei   = (const int*)d_in[1];   // int64 ref -> int32 on device
    const float* W0   = (const float*)d_in[2];
    const float* as0  = (const float*)d_in[3];
    const float* ad0  = (const float*)d_in[4];
    const float* b0   = (const float*)d_in[5];
    const float* W1   = (const float*)d_in[6];
    const float* as1  = (const float*)d_in[7];
    const float* ad1  = (const float*)d_in[8];
    const float* b1   = (const float*)d_in[9];
    float*       out  = (float*)d_out;

    const int TB = 256;
    const int nGrid    = (N_NODES + TB - 1) / TB;
    const int eGrid    = (E_TOT + TB - 1) / TB;
    const int gemmGrid = (N_NODES + GEMM_ROWS - 1) / GEMM_ROWS;
    const int gthGrid  = (N_NODES * 32 + TB - 1) / TB;

    dim3 gemmBlock(64, 4);

    // ---- CSR build (edge structure shared by both layers) ----
    zero_cnt_kernel<<<nGrid, TB>>>();
    hist_kernel<<<eGrid, TB>>>(ei);
    scan_kernel<<<1, 1024>>>();
    cursor_kernel<<<nGrid, TB>>>();
    scatter_kernel<<<eGrid, TB>>>(ei);

    // ---- layer 0 (gather writes g_x1 internally) ----
    gemm_alpha_kernel<<<gemmGrid, gemmBlock>>>(x, W0, as0, ad0, 0);
    gather_kernel<<<gthGrid, TB>>>(b0, x, out, 0);

    // ---- layer 1 ----
    gemm_alpha_kernel<<<gemmGrid, gemmBlock>>>(x, W1, as1, ad1, 1);
    gather_kernel<<<gthGrid, TB>>>(b1, x, out, 1);
}